// round 13
// baseline (speedup 1.0000x reference)
#include <cuda_runtime.h>

// Problem constants
#define B_TOT    4096
#define T_LEN    512
#define D_IN     7
#define H        64
#define G        256      // 4*H gates per layer
#define OUT_D    4
#define BTILE    32       // batch rows per CTA
#define NTHREADS 256      // thread = (8 batch rows) x (1 unit = 4 gates)
#define RP       36       // h smem pitch in floats
#define XP       32       // x smem pitch: s_x[d*XP + row]

typedef unsigned long long u64;

// group barrier: 64 threads (2 warps) of one batch-row group
#define GBAR(id) asm volatile("bar.sync %0, 64;" :: "r"(id) : "memory")

__device__ __forceinline__ u64 pack2(float v) {
    u64 r; asm("mov.b64 %0, {%1, %1};" : "=l"(r) : "f"(v)); return r;
}
__device__ __forceinline__ void unpack2(u64 v, float& a, float& b) {
    asm("mov.b64 {%0, %1}, %2;" : "=f"(a), "=f"(b) : "l"(v));
}
__device__ __forceinline__ u64 ffma2(u64 a, u64 b, u64 c) {
    u64 d; asm("fma.rn.f32x2 %0, %1, %2, %3;" : "=l"(d) : "l"(a), "l"(b), "l"(c)); return d;
}

// single-MUFU activations; sigmoid inputs arrive PRE-SCALED by 0.5
// (i/f/o weight rows and biases are multiplied by 0.5 at staging time):
//   sigma(z) = 0.5*tanh(z/2) + 0.5,  accumulator already holds z/2.
__device__ __forceinline__ float tanha(float x) {
    float y; asm("tanh.approx.f32 %0, %1;" : "=f"(y) : "f"(x)); return y;
}
__device__ __forceinline__ float sigp(float half_z) {
    return fmaf(tanha(half_z), 0.5f, 0.5f);
}

__global__ __launch_bounds__(NTHREADS, 1)
void lstm_fused_kernel(const float* __restrict__ x,
                       const float* __restrict__ W_ih0, const float* __restrict__ W_hh0,
                       const float* __restrict__ b_ih0, const float* __restrict__ b_hh0,
                       const float* __restrict__ W_ih1, const float* __restrict__ W_hh1,
                       const float* __restrict__ b_ih1, const float* __restrict__ b_hh1,
                       const float* __restrict__ W_fc,  const float* __restrict__ b_fc,
                       float* __restrict__ out)
{
    extern __shared__ float smem[];
    // weight layout: [k][unit][gate i,f,g,o] -> idx = k*256 + u*4 + g
    float* s_wih0 = smem;                    // [7][256]
    float* s_whh0 = s_wih0 + D_IN * G;       // [64][256]
    float* s_wih1 = s_whh0 + H * G;          // [64][256]
    float* s_whh1 = s_wih1 + H * G;          // [64][256]
    float* s_b0   = s_whh1 + H * G;          // [256]
    float* s_b1   = s_b0 + G;                // [256]
    float* s_wfc  = s_b1 + G;                // [4][64]
    float* s_bfc  = s_wfc + OUT_D * H;       // [8]
    float* s_h0   = s_bfc + 8;               // [64][RP]  [unit][row]
    float* s_h1   = s_h0 + H * RP;           // [64][RP]
    float* s_x    = s_h1 + H * RP;           // [7][XP]   [d][row]

    const int tid  = threadIdx.x;
    const int urow = tid >> 6;               // 0..3 : batch-row group (64 thr = 2 warps)
    const int ucol = tid & 63;               // 0..63: hidden unit
    const int r0   = urow * 8;               // first of this thread's 8 rows
    const int gbar = urow + 1;               // named barrier id for this group

    // ---- stage weights into smem, transposed + gate-interleaved ----
    // i/f/o rows (gb != 2) are pre-scaled by 0.5 for the sigmoid identity.
    for (int idx = tid; idx < D_IN * G; idx += NTHREADS) {
        int d = idx >> 8, r = idx & 255, u = r >> 2, gb = r & 3;
        float sc = (gb == 2) ? 1.0f : 0.5f;
        s_wih0[idx] = W_ih0[(gb * H + u) * D_IN + d] * sc;
    }
    for (int idx = tid; idx < H * G; idx += NTHREADS) {
        int k = idx >> 8, r = idx & 255, u = r >> 2, gb = r & 3;
        int row = gb * H + u;
        float sc = (gb == 2) ? 1.0f : 0.5f;
        s_whh0[idx] = W_hh0[row * H + k] * sc;
        s_wih1[idx] = W_ih1[row * H + k] * sc;
        s_whh1[idx] = W_hh1[row * H + k] * sc;
    }
    for (int r = tid; r < G; r += NTHREADS) {
        int u = r >> 2, gb = r & 3, row = gb * H + u;
        float sc = (gb == 2) ? 1.0f : 0.5f;
        s_b0[r] = (b_ih0[row] + b_hh0[row]) * sc;
        s_b1[r] = (b_ih1[row] + b_hh1[row]) * sc;
    }
    for (int i = tid; i < OUT_D * H; i += NTHREADS) s_wfc[i] = W_fc[i];
    if (tid < OUT_D) s_bfc[tid] = b_fc[tid];
    for (int i = tid; i < H * RP; i += NTHREADS) { s_h0[i] = 0.0f; s_h1[i] = 0.0f; }

    // x staging role, PER GROUP: 56 of 64 threads stage this group's 8 rows x 7 dims
    const int  bb      = blockIdx.x * BTILE;
    const bool xactive = ucol < 8 * D_IN;           // 56 stagers per group
    const int  xrl     = ucol / D_IN;               // local row 0..7
    const int  xd      = ucol - xrl * D_IN;         // dim 0..6
    const int  xrow    = r0 + xrl;                  // global row within tile
    const float* xg    = x + ((size_t)(bb + xrow) * T_LEN) * D_IN + xd;

    if (xactive) s_x[xd * XP + xrow] = __ldg(xg);   // prestage x[0]
    __syncthreads();                                 // weights + x[0] visible to all

    // bias packs per gate (duplicated into both FFMA2 lanes), once for all steps
    u64 b0g[4], b1g[4];
    {
        float4 t0 = *(const float4*)&s_b0[ucol * 4];
        b0g[0] = pack2(t0.x); b0g[1] = pack2(t0.y);
        b0g[2] = pack2(t0.z); b0g[3] = pack2(t0.w);
        float4 t1 = *(const float4*)&s_b1[ucol * 4];
        b1g[0] = pack2(t1.x); b1g[1] = pack2(t1.y);
        b1g[2] = pack2(t1.z); b1g[3] = pack2(t1.w);
    }

    float c0[8], c1[8];
    #pragma unroll
    for (int r = 0; r < 8; r++) { c0[r] = 0.f; c1[r] = 0.f; }

    // ============ prologue: t = 0 (h0old = h1old = 0 -> x-only gates) ============
    {
        u64 a0[16];
        #pragma unroll
        for (int g = 0; g < 4; g++)
            #pragma unroll
            for (int p = 0; p < 4; p++) a0[g * 4 + p] = b0g[g];

        #pragma unroll
        for (int d = 0; d < D_IN; d++) {
            float4 wv = *(const float4*)&s_wih0[d * G + ucol * 4];
            ulonglong2 xp = *(const ulonglong2*)&s_x[d * XP + r0];
            ulonglong2 xq = *(const ulonglong2*)&s_x[d * XP + r0 + 4];
            u64 xr[4] = {xp.x, xp.y, xq.x, xq.y};
            float ws[4] = {wv.x, wv.y, wv.z, wv.w};
            #pragma unroll
            for (int g = 0; g < 4; g++) {
                u64 wp = pack2(ws[g]);
                #pragma unroll
                for (int p = 0; p < 4; p++)
                    a0[g * 4 + p] = ffma2(wp, xr[p], a0[g * 4 + p]);
            }
        }

        float h0nv[8];
        #pragma unroll
        for (int p = 0; p < 4; p++) {
            float i0, i1, f0, f1, g0, g1, o0, o1;
            unpack2(a0[0 + p],  i0, i1);
            unpack2(a0[4 + p],  f0, f1);
            unpack2(a0[8 + p],  g0, g1);
            unpack2(a0[12 + p], o0, o1);
            c0[2*p]   = sigp(f0) * c0[2*p]   + sigp(i0) * tanha(g0);
            h0nv[2*p]   = sigp(o0) * tanha(c0[2*p]);
            c0[2*p+1] = sigp(f1) * c0[2*p+1] + sigp(i1) * tanha(g1);
            h0nv[2*p+1] = sigp(o1) * tanha(c0[2*p+1]);
        }

        GBAR(gbar);   // group's reads of s_x[0] done
        *(float4*)&s_h0[ucol * RP + r0]     = make_float4(h0nv[0], h0nv[1], h0nv[2], h0nv[3]);
        *(float4*)&s_h0[ucol * RP + r0 + 4] = make_float4(h0nv[4], h0nv[5], h0nv[6], h0nv[7]);
        if (xactive) s_x[xd * XP + xrow] = __ldg(xg + D_IN);   // stage x[1]
        GBAR(gbar);
    }

    // ============ main loop: iteration t computes h0(t) and h1(t-1) ============
    for (int t = 1; t < T_LEN; t++) {
        // prefetch x(t+1) into register; latency overlaps the whole step
        float xnext = 0.0f;
        if (xactive && t + 1 < T_LEN) xnext = __ldg(xg + (size_t)(t + 1) * D_IN);

        // ---------- phase A: a0 = b0 + Wih0@x(t) + Whh0@h0old ----------
        u64 a0[16];
        #pragma unroll
        for (int g = 0; g < 4; g++)
            #pragma unroll
            for (int p = 0; p < 4; p++) a0[g * 4 + p] = b0g[g];

        #pragma unroll
        for (int d = 0; d < D_IN; d++) {
            float4 wv = *(const float4*)&s_wih0[d * G + ucol * 4];
            ulonglong2 xp = *(const ulonglong2*)&s_x[d * XP + r0];
            ulonglong2 xq = *(const ulonglong2*)&s_x[d * XP + r0 + 4];
            u64 xr[4] = {xp.x, xp.y, xq.x, xq.y};
            float ws[4] = {wv.x, wv.y, wv.z, wv.w};
            #pragma unroll
            for (int g = 0; g < 4; g++) {
                u64 wp = pack2(ws[g]);
                #pragma unroll
                for (int p = 0; p < 4; p++)
                    a0[g * 4 + p] = ffma2(wp, xr[p], a0[g * 4 + p]);
            }
        }

        #pragma unroll 8
        for (int k = 0; k < H; k++) {
            float4 w0v = *(const float4*)&s_whh0[k * G + ucol * 4];
            ulonglong2 h0p = *(const ulonglong2*)&s_h0[k * RP + r0];
            ulonglong2 h0q = *(const ulonglong2*)&s_h0[k * RP + r0 + 4];
            u64 h0r[4] = {h0p.x, h0p.y, h0q.x, h0q.y};
            float w0s[4] = {w0v.x, w0v.y, w0v.z, w0v.w};
            #pragma unroll
            for (int g = 0; g < 4; g++) {
                u64 w0p = pack2(w0s[g]);
                #pragma unroll
                for (int p = 0; p < 4; p++)
                    a0[g * 4 + p] = ffma2(w0p, h0r[p], a0[g * 4 + p]);
            }
        }

        // ---------- phase B: layer-0 activations (overlap with phase C issue) ----------
        float h0nv[8];
        #pragma unroll
        for (int p = 0; p < 4; p++) {
            float i0, i1, f0, f1, g0, g1, o0, o1;
            unpack2(a0[0 + p],  i0, i1);
            unpack2(a0[4 + p],  f0, f1);
            unpack2(a0[8 + p],  g0, g1);
            unpack2(a0[12 + p], o0, o1);
            c0[2*p]   = sigp(f0) * c0[2*p]   + sigp(i0) * tanha(g0);
            h0nv[2*p]   = sigp(o0) * tanha(c0[2*p]);
            c0[2*p+1] = sigp(f1) * c0[2*p+1] + sigp(i1) * tanha(g1);
            h0nv[2*p+1] = sigp(o1) * tanha(c0[2*p+1]);
        }

        // ---------- phase C: a1 = b1 + Wih1@h0old + Whh1@h1old ----------
        u64 a1[16];
        #pragma unroll
        for (int g = 0; g < 4; g++)
            #pragma unroll
            for (int p = 0; p < 4; p++) a1[g * 4 + p] = b1g[g];

        #pragma unroll 4
        for (int k = 0; k < H; k++) {
            float4 w1v = *(const float4*)&s_whh1[k * G + ucol * 4];
            float4 w2v = *(const float4*)&s_wih1[k * G + ucol * 4];
            ulonglong2 h0p = *(const ulonglong2*)&s_h0[k * RP + r0];
            ulonglong2 h0q = *(const ulonglong2*)&s_h0[k * RP + r0 + 4];
            ulonglong2 h1p = *(const ulonglong2*)&s_h1[k * RP + r0];
            ulonglong2 h1q = *(const ulonglong2*)&s_h1[k * RP + r0 + 4];
            u64 h0r[4] = {h0p.x, h0p.y, h0q.x, h0q.y};
            u64 h1r[4] = {h1p.x, h1p.y, h1q.x, h1q.y};
            float w1s[4] = {w1v.x, w1v.y, w1v.z, w1v.w};
            float w2s[4] = {w2v.x, w2v.y, w2v.z, w2v.w};
            #pragma unroll
            for (int g = 0; g < 4; g++) {
                u64 w2p = pack2(w2s[g]);
                u64 w1p = pack2(w1s[g]);
                #pragma unroll
                for (int p = 0; p < 4; p++)
                    a1[g * 4 + p] = ffma2(w2p, h0r[p], a1[g * 4 + p]);
                #pragma unroll
                for (int p = 0; p < 4; p++)
                    a1[g * 4 + p] = ffma2(w1p, h1r[p], a1[g * 4 + p]);
            }
        }

        // ---------- phase D: layer-1 activations ----------
        float h1nv[8];
        #pragma unroll
        for (int p = 0; p < 4; p++) {
            float I0, I1, F0, F1, G0, G1, O0, O1;
            unpack2(a1[0 + p],  I0, I1);
            unpack2(a1[4 + p],  F0, F1);
            unpack2(a1[8 + p],  G0, G1);
            unpack2(a1[12 + p], O0, O1);
            c1[2*p]   = sigp(F0) * c1[2*p]   + sigp(I0) * tanha(G0);
            h1nv[2*p]   = sigp(O0) * tanha(c1[2*p]);
            c1[2*p+1] = sigp(F1) * c1[2*p+1] + sigp(I1) * tanha(G1);
            h1nv[2*p+1] = sigp(O1) * tanha(c1[2*p+1]);
        }

        GBAR(gbar);   // group's reads of s_h0/s_h1/s_x for this step done
        *(float4*)&s_h0[ucol * RP + r0]     = make_float4(h0nv[0], h0nv[1], h0nv[2], h0nv[3]);
        *(float4*)&s_h0[ucol * RP + r0 + 4] = make_float4(h0nv[4], h0nv[5], h0nv[6], h0nv[7]);
        *(float4*)&s_h1[ucol * RP + r0]     = make_float4(h1nv[0], h1nv[1], h1nv[2], h1nv[3]);
        *(float4*)&s_h1[ucol * RP + r0 + 4] = make_float4(h1nv[4], h1nv[5], h1nv[6], h1nv[7]);

        // stage prefetched x(t+1)
        if (xactive && t + 1 < T_LEN)
            s_x[xd * XP + xrow] = xnext;

        GBAR(gbar);   // group's new h0/h1/x visible before next iteration
    }

    // ---- pipeline drain: compute h1(T-1) from h0(T-1), h1(T-2) ----
    {
        u64 a1[16];
        #pragma unroll
        for (int g = 0; g < 4; g++)
            #pragma unroll
            for (int p = 0; p < 4; p++) a1[g * 4 + p] = b1g[g];

        #pragma unroll 4
        for (int k = 0; k < H; k++) {
            float4 w1v = *(const float4*)&s_whh1[k * G + ucol * 4];
            float4 w2v = *(const float4*)&s_wih1[k * G + ucol * 4];
            ulonglong2 h0p = *(const ulonglong2*)&s_h0[k * RP + r0];
            ulonglong2 h0q = *(const ulonglong2*)&s_h0[k * RP + r0 + 4];
            ulonglong2 h1p = *(const ulonglong2*)&s_h1[k * RP + r0];
            ulonglong2 h1q = *(const ulonglong2*)&s_h1[k * RP + r0 + 4];
            u64 h0r[4] = {h0p.x, h0p.y, h0q.x, h0q.y};
            u64 h1r[4] = {h1p.x, h1p.y, h1q.x, h1q.y};
            float w1s[4] = {w1v.x, w1v.y, w1v.z, w1v.w};
            float w2s[4] = {w2v.x, w2v.y, w2v.z, w2v.w};
            #pragma unroll
            for (int g = 0; g < 4; g++) {
                u64 w2p = pack2(w2s[g]);
                u64 w1p = pack2(w1s[g]);
                #pragma unroll
                for (int p = 0; p < 4; p++)
                    a1[g * 4 + p] = ffma2(w2p, h0r[p], a1[g * 4 + p]);
                #pragma unroll
                for (int p = 0; p < 4; p++)
                    a1[g * 4 + p] = ffma2(w1p, h1r[p], a1[g * 4 + p]);
            }
        }

        float h1nv[8];
        #pragma unroll
        for (int p = 0; p < 4; p++) {
            float I0, I1, F0, F1, G0, G1, O0, O1;
            unpack2(a1[0 + p],  I0, I1);
            unpack2(a1[4 + p],  F0, F1);
            unpack2(a1[8 + p],  G0, G1);
            unpack2(a1[12 + p], O0, O1);
            c1[2*p]   = sigp(F0) * c1[2*p]   + sigp(I0) * tanha(G0);
            h1nv[2*p]   = sigp(O0) * tanha(c1[2*p]);
            c1[2*p+1] = sigp(F1) * c1[2*p+1] + sigp(I1) * tanha(G1);
            h1nv[2*p+1] = sigp(O1) * tanha(c1[2*p+1]);
        }
        GBAR(gbar);   // group's reads of s_h1 (h1(T-2)) done
        *(float4*)&s_h1[ucol * RP + r0]     = make_float4(h1nv[0], h1nv[1], h1nv[2], h1nv[3]);
        *(float4*)&s_h1[ucol * RP + r0 + 4] = make_float4(h1nv[4], h1nv[5], h1nv[6], h1nv[7]);
        __syncthreads();   // ALL groups' final h1 visible for the epilogue
    }

    // ---- epilogue: out[b] = h1_last @ W_fc^T + b_fc (warp 0, lane = row) ----
    if (tid < 32) {
        float acc[OUT_D];
        #pragma unroll
        for (int o = 0; o < OUT_D; o++) acc[o] = s_bfc[o];
        #pragma unroll 8
        for (int k = 0; k < H; k++) {
            float hv = s_h1[k * RP + tid];   // h1[row=tid][k]
            #pragma unroll
            for (int o = 0; o < OUT_D; o++) acc[o] += hv * s_wfc[o * H + k];
        }
        int b = bb + tid;
        #pragma unroll
        for (int o = 0; o < OUT_D; o++)
            out[(size_t)b * OUT_D + o] = acc[o];
    }
}

extern "C" void kernel_launch(void* const* d_in, const int* in_sizes, int n_in,
                              void* d_out, int out_size)
{
    const float* x     = (const float*)d_in[0];
    const float* W_ih0 = (const float*)d_in[1];
    const float* W_hh0 = (const float*)d_in[2];
    const float* b_ih0 = (const float*)d_in[3];
    const float* b_hh0 = (const float*)d_in[4];
    const float* W_ih1 = (const float*)d_in[5];
    const float* W_hh1 = (const float*)d_in[6];
    const float* b_ih1 = (const float*)d_in[7];
    const float* b_hh1 = (const float*)d_in[8];
    const float* W_fc  = (const float*)d_in[9];
    const float* b_fc  = (const float*)d_in[10];
    float* out = (float*)d_out;

    const size_t smem_floats = (size_t)D_IN * G + 3 * (size_t)H * G + 2 * G
                             + OUT_D * H + 8 + 2 * (size_t)H * RP + D_IN * XP;
    const size_t smem_bytes = smem_floats * sizeof(float);   // 226,208 B

    cudaFuncSetAttribute(lstm_fused_kernel,
                         cudaFuncAttributeMaxDynamicSharedMemorySize,
                         (int)smem_bytes);

    lstm_fused_kernel<<<B_TOT / BTILE, NTHREADS, smem_bytes>>>(
        x, W_ih0, W_hh0, b_ih0, b_hh0,
        W_ih1, W_hh1, b_ih1, b_hh1, W_fc, b_fc, out);
}

// round 14
// speedup vs baseline: 1.0379x; 1.0379x over previous
#include <cuda_runtime.h>

// Problem constants
#define B_TOT    4096
#define T_LEN    512
#define D_IN     7
#define H        64
#define G        256      // 4*H gates per layer
#define OUT_D    4
#define BTILE    32       // batch rows per CTA
#define NTHREADS 256      // thread = (8 batch rows) x (1 unit = 4 gates)
#define RP       36       // h smem pitch in floats
#define XP       32       // x smem pitch: s_x[d*XP + row]

typedef unsigned long long u64;

// group barrier: 64 threads (2 warps) of one batch-row group
#define GBAR(id) asm volatile("bar.sync %0, 64;" :: "r"(id) : "memory")

__device__ __forceinline__ u64 pack2(float v) {
    u64 r; asm("mov.b64 %0, {%1, %1};" : "=l"(r) : "f"(v)); return r;
}
__device__ __forceinline__ void unpack2(u64 v, float& a, float& b) {
    asm("mov.b64 {%0, %1}, %2;" : "=f"(a), "=f"(b) : "l"(v));
}
__device__ __forceinline__ u64 ffma2(u64 a, u64 b, u64 c) {
    u64 d; asm("fma.rn.f32x2 %0, %1, %2, %3;" : "=l"(d) : "l"(a), "l"(b), "l"(c)); return d;
}

// single-MUFU activations; sigmoid inputs arrive PRE-SCALED by 0.5
// (i/f/o weight rows and biases are multiplied by 0.5 at staging time):
//   sigma(z) = 0.5*tanh(z/2) + 0.5,  accumulator already holds z/2.
__device__ __forceinline__ float tanha(float x) {
    float y; asm("tanh.approx.f32 %0, %1;" : "=f"(y) : "f"(x)); return y;
}
__device__ __forceinline__ float sigp(float half_z) {
    return fmaf(tanha(half_z), 0.5f, 0.5f);
}

__global__ __launch_bounds__(NTHREADS, 1)
void lstm_fused_kernel(const float* __restrict__ x,
                       const float* __restrict__ W_ih0, const float* __restrict__ W_hh0,
                       const float* __restrict__ b_ih0, const float* __restrict__ b_hh0,
                       const float* __restrict__ W_ih1, const float* __restrict__ W_hh1,
                       const float* __restrict__ b_ih1, const float* __restrict__ b_hh1,
                       const float* __restrict__ W_fc,  const float* __restrict__ b_fc,
                       float* __restrict__ out)
{
    extern __shared__ float smem[];
    // weight layout: [k][unit][gate i,f,g,o] -> idx = k*256 + u*4 + g
    float* s_wih0 = smem;                    // [7][256]
    float* s_whh0 = s_wih0 + D_IN * G;       // [64][256]
    float* s_wih1 = s_whh0 + H * G;          // [64][256]
    float* s_whh1 = s_wih1 + H * G;          // [64][256]
    float* s_b0   = s_whh1 + H * G;          // [256]
    float* s_b1   = s_b0 + G;                // [256]
    float* s_wfc  = s_b1 + G;                // [4][64]
    float* s_bfc  = s_wfc + OUT_D * H;       // [8]
    float* s_h0   = s_bfc + 8;               // [64][RP]  [unit][row]
    float* s_h1   = s_h0 + H * RP;           // [64][RP]
    float* s_x    = s_h1 + H * RP;           // [7][XP]   [d][row]

    const int tid  = threadIdx.x;
    const int urow = tid >> 6;               // 0..3 : batch-row group (64 thr = 2 warps)
    const int ucol = tid & 63;               // 0..63: hidden unit
    const int r0   = urow * 8;               // first of this thread's 8 rows
    const int gbar = urow + 1;               // named barrier id for this group

    // ---- stage weights into smem, transposed + gate-interleaved ----
    // i/f/o rows (gb != 2) are pre-scaled by 0.5 for the sigmoid identity.
    for (int idx = tid; idx < D_IN * G; idx += NTHREADS) {
        int d = idx >> 8, r = idx & 255, u = r >> 2, gb = r & 3;
        float sc = (gb == 2) ? 1.0f : 0.5f;
        s_wih0[idx] = W_ih0[(gb * H + u) * D_IN + d] * sc;
    }
    for (int idx = tid; idx < H * G; idx += NTHREADS) {
        int k = idx >> 8, r = idx & 255, u = r >> 2, gb = r & 3;
        int row = gb * H + u;
        float sc = (gb == 2) ? 1.0f : 0.5f;
        s_whh0[idx] = W_hh0[row * H + k] * sc;
        s_wih1[idx] = W_ih1[row * H + k] * sc;
        s_whh1[idx] = W_hh1[row * H + k] * sc;
    }
    for (int r = tid; r < G; r += NTHREADS) {
        int u = r >> 2, gb = r & 3, row = gb * H + u;
        float sc = (gb == 2) ? 1.0f : 0.5f;
        s_b0[r] = (b_ih0[row] + b_hh0[row]) * sc;
        s_b1[r] = (b_ih1[row] + b_hh1[row]) * sc;
    }
    for (int i = tid; i < OUT_D * H; i += NTHREADS) s_wfc[i] = W_fc[i];
    if (tid < OUT_D) s_bfc[tid] = b_fc[tid];
    for (int i = tid; i < H * RP; i += NTHREADS) { s_h0[i] = 0.0f; s_h1[i] = 0.0f; }

    // x staging role, PER GROUP: 56 of 64 threads stage this group's 8 rows x 7 dims
    const int  bb      = blockIdx.x * BTILE;
    const bool xactive = ucol < 8 * D_IN;           // 56 stagers per group
    const int  xrl     = ucol / D_IN;               // local row 0..7
    const int  xd      = ucol - xrl * D_IN;         // dim 0..6
    const int  xrow    = r0 + xrl;                  // global row within tile
    const float* xg    = x + ((size_t)(bb + xrow) * T_LEN) * D_IN + xd;

    if (xactive) s_x[xd * XP + xrow] = __ldg(xg);   // prestage x[0]
    __syncthreads();                                 // weights + x[0] visible to all

    // bias packs per gate (duplicated into both FFMA2 lanes), once for all steps
    u64 b0g[4], b1g[4];
    {
        float4 t0 = *(const float4*)&s_b0[ucol * 4];
        b0g[0] = pack2(t0.x); b0g[1] = pack2(t0.y);
        b0g[2] = pack2(t0.z); b0g[3] = pack2(t0.w);
        float4 t1 = *(const float4*)&s_b1[ucol * 4];
        b1g[0] = pack2(t1.x); b1g[1] = pack2(t1.y);
        b1g[2] = pack2(t1.z); b1g[3] = pack2(t1.w);
    }

    float c0[8], c1[8];
    #pragma unroll
    for (int r = 0; r < 8; r++) { c0[r] = 0.f; c1[r] = 0.f; }

    // ============ prologue: t = 0 (h0old = h1old = 0 -> x-only gates) ============
    {
        u64 a0[16];
        #pragma unroll
        for (int g = 0; g < 4; g++)
            #pragma unroll
            for (int p = 0; p < 4; p++) a0[g * 4 + p] = b0g[g];

        #pragma unroll
        for (int d = 0; d < D_IN; d++) {
            float4 wv = *(const float4*)&s_wih0[d * G + ucol * 4];
            ulonglong2 xp = *(const ulonglong2*)&s_x[d * XP + r0];
            ulonglong2 xq = *(const ulonglong2*)&s_x[d * XP + r0 + 4];
            u64 xr[4] = {xp.x, xp.y, xq.x, xq.y};
            float ws[4] = {wv.x, wv.y, wv.z, wv.w};
            #pragma unroll
            for (int g = 0; g < 4; g++) {
                u64 wp = pack2(ws[g]);
                #pragma unroll
                for (int p = 0; p < 4; p++)
                    a0[g * 4 + p] = ffma2(wp, xr[p], a0[g * 4 + p]);
            }
        }

        float h0nv[8];
        #pragma unroll
        for (int p = 0; p < 4; p++) {
            float i0, i1, f0, f1, g0, g1, o0, o1;
            unpack2(a0[0 + p],  i0, i1);
            unpack2(a0[4 + p],  f0, f1);
            unpack2(a0[8 + p],  g0, g1);
            unpack2(a0[12 + p], o0, o1);
            c0[2*p]   = sigp(f0) * c0[2*p]   + sigp(i0) * tanha(g0);
            h0nv[2*p]   = sigp(o0) * tanha(c0[2*p]);
            c0[2*p+1] = sigp(f1) * c0[2*p+1] + sigp(i1) * tanha(g1);
            h0nv[2*p+1] = sigp(o1) * tanha(c0[2*p+1]);
        }

        GBAR(gbar);   // group's reads of s_x[0] done
        *(float4*)&s_h0[ucol * RP + r0]     = make_float4(h0nv[0], h0nv[1], h0nv[2], h0nv[3]);
        *(float4*)&s_h0[ucol * RP + r0 + 4] = make_float4(h0nv[4], h0nv[5], h0nv[6], h0nv[7]);
        if (xactive) s_x[xd * XP + xrow] = __ldg(xg + D_IN);   // stage x[1]
        GBAR(gbar);
    }

    // ============ main loop: iteration t computes h0(t) and h1(t-1) ============
    for (int t = 1; t < T_LEN; t++) {
        // prefetch x(t+1) into register; latency overlaps the whole step
        float xnext = 0.0f;
        if (xactive && t + 1 < T_LEN) xnext = __ldg(xg + (size_t)(t + 1) * D_IN);

        u64 a0[16], a1[16];
        #pragma unroll
        for (int g = 0; g < 4; g++)
            #pragma unroll
            for (int p = 0; p < 4; p++) {
                a0[g * 4 + p] = b0g[g];
                a1[g * 4 + p] = b1g[g];
            }

        // x(t) @ W_ih0^T FIRST: its LDS latency hides under the long k-loop,
        // and it no longer sits on the dependency path right before activations.
        #pragma unroll
        for (int d = 0; d < D_IN; d++) {
            float4 wv = *(const float4*)&s_wih0[d * G + ucol * 4];
            ulonglong2 xp = *(const ulonglong2*)&s_x[d * XP + r0];
            ulonglong2 xq = *(const ulonglong2*)&s_x[d * XP + r0 + 4];
            u64 xr[4] = {xp.x, xp.y, xq.x, xq.y};
            float ws[4] = {wv.x, wv.y, wv.z, wv.w};
            #pragma unroll
            for (int g = 0; g < 4; g++) {
                u64 wp = pack2(ws[g]);
                #pragma unroll
                for (int p = 0; p < 4; p++)
                    a0[g * 4 + p] = ffma2(wp, xr[p], a0[g * 4 + p]);
            }
        }

        // ---- fused GEMMs: Whh0@h0old, Wih1@h0old, Whh1@h1old ----
        #pragma unroll 4
        for (int k = 0; k < H; k++) {
            float4 w0v = *(const float4*)&s_whh0[k * G + ucol * 4];
            float4 w1v = *(const float4*)&s_whh1[k * G + ucol * 4];
            float4 w2v = *(const float4*)&s_wih1[k * G + ucol * 4];
            ulonglong2 h0p = *(const ulonglong2*)&s_h0[k * RP + r0];
            ulonglong2 h0q = *(const ulonglong2*)&s_h0[k * RP + r0 + 4];
            ulonglong2 h1p = *(const ulonglong2*)&s_h1[k * RP + r0];
            ulonglong2 h1q = *(const ulonglong2*)&s_h1[k * RP + r0 + 4];
            u64 h0r[4] = {h0p.x, h0p.y, h0q.x, h0q.y};
            u64 h1r[4] = {h1p.x, h1p.y, h1q.x, h1q.y};
            float w0s[4] = {w0v.x, w0v.y, w0v.z, w0v.w};
            float w1s[4] = {w1v.x, w1v.y, w1v.z, w1v.w};
            float w2s[4] = {w2v.x, w2v.y, w2v.z, w2v.w};
            #pragma unroll
            for (int g = 0; g < 4; g++) {
                u64 w0p = pack2(w0s[g]);
                u64 w2p = pack2(w2s[g]);
                u64 w1p = pack2(w1s[g]);
                #pragma unroll
                for (int p = 0; p < 4; p++)
                    a0[g * 4 + p] = ffma2(w0p, h0r[p], a0[g * 4 + p]);
                #pragma unroll
                for (int p = 0; p < 4; p++)
                    a1[g * 4 + p] = ffma2(w2p, h0r[p], a1[g * 4 + p]);
                #pragma unroll
                for (int p = 0; p < 4; p++)
                    a1[g * 4 + p] = ffma2(w1p, h1r[p], a1[g * 4 + p]);
            }
        }

        // ---- both cell updates, interleaved (independent MUFU chains) ----
        float h0nv[8], h1nv[8];
        #pragma unroll
        for (int p = 0; p < 4; p++) {
            float i0, i1, f0, f1, g0, g1, o0, o1;
            unpack2(a0[0 + p],  i0, i1);
            unpack2(a0[4 + p],  f0, f1);
            unpack2(a0[8 + p],  g0, g1);
            unpack2(a0[12 + p], o0, o1);
            c0[2*p]   = sigp(f0) * c0[2*p]   + sigp(i0) * tanha(g0);
            h0nv[2*p]   = sigp(o0) * tanha(c0[2*p]);
            c0[2*p+1] = sigp(f1) * c0[2*p+1] + sigp(i1) * tanha(g1);
            h0nv[2*p+1] = sigp(o1) * tanha(c0[2*p+1]);

            float I0, I1, F0, F1, G0, G1, O0, O1;
            unpack2(a1[0 + p],  I0, I1);
            unpack2(a1[4 + p],  F0, F1);
            unpack2(a1[8 + p],  G0, G1);
            unpack2(a1[12 + p], O0, O1);
            c1[2*p]   = sigp(F0) * c1[2*p]   + sigp(I0) * tanha(G0);
            h1nv[2*p]   = sigp(O0) * tanha(c1[2*p]);
            c1[2*p+1] = sigp(F1) * c1[2*p+1] + sigp(I1) * tanha(G1);
            h1nv[2*p+1] = sigp(O1) * tanha(c1[2*p+1]);
        }

        GBAR(gbar);   // group's reads of s_h0/s_h1/s_x for this step done
        *(float4*)&s_h0[ucol * RP + r0]     = make_float4(h0nv[0], h0nv[1], h0nv[2], h0nv[3]);
        *(float4*)&s_h0[ucol * RP + r0 + 4] = make_float4(h0nv[4], h0nv[5], h0nv[6], h0nv[7]);
        *(float4*)&s_h1[ucol * RP + r0]     = make_float4(h1nv[0], h1nv[1], h1nv[2], h1nv[3]);
        *(float4*)&s_h1[ucol * RP + r0 + 4] = make_float4(h1nv[4], h1nv[5], h1nv[6], h1nv[7]);

        // stage prefetched x(t+1)
        if (xactive && t + 1 < T_LEN)
            s_x[xd * XP + xrow] = xnext;

        GBAR(gbar);   // group's new h0/h1/x visible before next iteration
    }

    // ---- pipeline drain: compute h1(T-1) from h0(T-1), h1(T-2) ----
    {
        u64 a1[16];
        #pragma unroll
        for (int g = 0; g < 4; g++)
            #pragma unroll
            for (int p = 0; p < 4; p++) a1[g * 4 + p] = b1g[g];

        #pragma unroll 4
        for (int k = 0; k < H; k++) {
            float4 w1v = *(const float4*)&s_whh1[k * G + ucol * 4];
            float4 w2v = *(const float4*)&s_wih1[k * G + ucol * 4];
            ulonglong2 h0p = *(const ulonglong2*)&s_h0[k * RP + r0];
            ulonglong2 h0q = *(const ulonglong2*)&s_h0[k * RP + r0 + 4];
            ulonglong2 h1p = *(const ulonglong2*)&s_h1[k * RP + r0];
            ulonglong2 h1q = *(const ulonglong2*)&s_h1[k * RP + r0 + 4];
            u64 h0r[4] = {h0p.x, h0p.y, h0q.x, h0q.y};
            u64 h1r[4] = {h1p.x, h1p.y, h1q.x, h1q.y};
            float w1s[4] = {w1v.x, w1v.y, w1v.z, w1v.w};
            float w2s[4] = {w2v.x, w2v.y, w2v.z, w2v.w};
            #pragma unroll
            for (int g = 0; g < 4; g++) {
                u64 w2p = pack2(w2s[g]);
                u64 w1p = pack2(w1s[g]);
                #pragma unroll
                for (int p = 0; p < 4; p++)
                    a1[g * 4 + p] = ffma2(w2p, h0r[p], a1[g * 4 + p]);
                #pragma unroll
                for (int p = 0; p < 4; p++)
                    a1[g * 4 + p] = ffma2(w1p, h1r[p], a1[g * 4 + p]);
            }
        }

        float h1nv[8];
        #pragma unroll
        for (int p = 0; p < 4; p++) {
            float I0, I1, F0, F1, G0, G1, O0, O1;
            unpack2(a1[0 + p],  I0, I1);
            unpack2(a1[4 + p],  F0, F1);
            unpack2(a1[8 + p],  G0, G1);
            unpack2(a1[12 + p], O0, O1);
            c1[2*p]   = sigp(F0) * c1[2*p]   + sigp(I0) * tanha(G0);
            h1nv[2*p]   = sigp(O0) * tanha(c1[2*p]);
            c1[2*p+1] = sigp(F1) * c1[2*p+1] + sigp(I1) * tanha(G1);
            h1nv[2*p+1] = sigp(O1) * tanha(c1[2*p+1]);
        }
        GBAR(gbar);   // group's reads of s_h1 (h1(T-2)) done
        *(float4*)&s_h1[ucol * RP + r0]     = make_float4(h1nv[0], h1nv[1], h1nv[2], h1nv[3]);
        *(float4*)&s_h1[ucol * RP + r0 + 4] = make_float4(h1nv[4], h1nv[5], h1nv[6], h1nv[7]);
        __syncthreads();   // ALL groups' final h1 visible for the epilogue
    }

    // ---- epilogue: out[b] = h1_last @ W_fc^T + b_fc (warp 0, lane = row) ----
    if (tid < 32) {
        float acc[OUT_D];
        #pragma unroll
        for (int o = 0; o < OUT_D; o++) acc[o] = s_bfc[o];
        #pragma unroll 8
        for (int k = 0; k < H; k++) {
            float hv = s_h1[k * RP + tid];   // h1[row=tid][k]
            #pragma unroll
            for (int o = 0; o < OUT_D; o++) acc[o] += hv * s_wfc[o * H + k];
        }
        int b = bb + tid;
        #pragma unroll
        for (int o = 0; o < OUT_D; o++)
            out[(size_t)b * OUT_D + o] = acc[o];
    }
}

extern "C" void kernel_launch(void* const* d_in, const int* in_sizes, int n_in,
                              void* d_out, int out_size)
{
    const float* x     = (const float*)d_in[0];
    const float* W_ih0 = (const float*)d_in[1];
    const float* W_hh0 = (const float*)d_in[2];
    const float* b_ih0 = (const float*)d_in[3];
    const float* b_hh0 = (const float*)d_in[4];
    const float* W_ih1 = (const float*)d_in[5];
    const float* W_hh1 = (const float*)d_in[6];
    const float* b_ih1 = (const float*)d_in[7];
    const float* b_hh1 = (const float*)d_in[8];
    const float* W_fc  = (const float*)d_in[9];
    const float* b_fc  = (const float*)d_in[10];
    float* out = (float*)d_out;

    const size_t smem_floats = (size_t)D_IN * G + 3 * (size_t)H * G + 2 * G
                             + OUT_D * H + 8 + 2 * (size_t)H * RP + D_IN * XP;
    const size_t smem_bytes = smem_floats * sizeof(float);   // 226,208 B

    cudaFuncSetAttribute(lstm_fused_kernel,
                         cudaFuncAttributeMaxDynamicSharedMemorySize,
                         (int)smem_bytes);

    lstm_fused_kernel<<<B_TOT / BTILE, NTHREADS, smem_bytes>>>(
        x, W_ih0, W_hh0, b_ih0, b_hh0,
        W_ih1, W_hh1, b_ih1, b_hh1, W_fc, b_fc, out);
}

// round 15
// speedup vs baseline: 1.0502x; 1.0118x over previous
#include <cuda_runtime.h>

// Problem constants
#define B_TOT    4096
#define T_LEN    512
#define D_IN     7
#define H        64
#define G        256      // 4*H gates per layer
#define OUT_D    4
#define BTILE    32       // batch rows per CTA
#define NTHREADS 256      // thread = (8 batch rows) x (1 unit = 4 gates)
#define RP       36       // h smem pitch in floats
#define XP       32       // x smem pitch: s_x[d*XP + row]

typedef unsigned long long u64;

// group barrier: 64 threads (2 warps) of one batch-row group
#define GBAR(id) asm volatile("bar.sync %0, 64;" :: "r"(id) : "memory")

__device__ __forceinline__ u64 pack2(float v) {
    u64 r; asm("mov.b64 %0, {%1, %1};" : "=l"(r) : "f"(v)); return r;
}
__device__ __forceinline__ void unpack2(u64 v, float& a, float& b) {
    asm("mov.b64 {%0, %1}, %2;" : "=f"(a), "=f"(b) : "l"(v));
}
__device__ __forceinline__ u64 ffma2(u64 a, u64 b, u64 c) {
    u64 d; asm("fma.rn.f32x2 %0, %1, %2, %3;" : "=l"(d) : "l"(a), "l"(b), "l"(c)); return d;
}

// single-MUFU activations; sigmoid inputs arrive PRE-SCALED by 0.5
// (i/f/o weight rows and biases are multiplied by 0.5 at staging time):
//   sigma(z) = 0.5*tanh(z/2) + 0.5,  accumulator already holds z/2.
__device__ __forceinline__ float tanha(float x) {
    float y; asm("tanh.approx.f32 %0, %1;" : "=f"(y) : "f"(x)); return y;
}
__device__ __forceinline__ float sigp(float half_z) {
    return fmaf(tanha(half_z), 0.5f, 0.5f);
}

__global__ __launch_bounds__(NTHREADS, 1)
void lstm_fused_kernel(const float* __restrict__ x,
                       const float* __restrict__ W_ih0, const float* __restrict__ W_hh0,
                       const float* __restrict__ b_ih0, const float* __restrict__ b_hh0,
                       const float* __restrict__ W_ih1, const float* __restrict__ W_hh1,
                       const float* __restrict__ b_ih1, const float* __restrict__ b_hh1,
                       const float* __restrict__ W_fc,  const float* __restrict__ b_fc,
                       float* __restrict__ out)
{
    extern __shared__ float smem[];
    // weight layout: [k][unit][gate i,f,g,o] -> idx = k*256 + u*4 + g
    float* s_wih0 = smem;                    // [7][256]
    float* s_whh0 = s_wih0 + D_IN * G;       // [64][256]
    float* s_wih1 = s_whh0 + H * G;          // [64][256]
    float* s_whh1 = s_wih1 + H * G;          // [64][256]
    float* s_b0   = s_whh1 + H * G;          // [256]
    float* s_b1   = s_b0 + G;                // [256]
    float* s_wfc  = s_b1 + G;                // [4][64]
    float* s_bfc  = s_wfc + OUT_D * H;       // [8]
    float* s_h0   = s_bfc + 8;               // [64][RP]  [unit][row]
    float* s_h1   = s_h0 + H * RP;           // [64][RP]
    float* s_x    = s_h1 + H * RP;           // [7][XP]   [d][row]

    const int tid  = threadIdx.x;
    const int urow = tid >> 6;               // 0..3 : batch-row group (64 thr = 2 warps)
    const int ucol = tid & 63;               // 0..63: hidden unit
    const int r0   = urow * 8;               // first of this thread's 8 rows
    const int gbar = urow + 1;               // named barrier id for this group

    // ---- stage weights into smem, transposed + gate-interleaved ----
    // i/f/o rows (gb != 2) are pre-scaled by 0.5 for the sigmoid identity.
    for (int idx = tid; idx < D_IN * G; idx += NTHREADS) {
        int d = idx >> 8, r = idx & 255, u = r >> 2, gb = r & 3;
        float sc = (gb == 2) ? 1.0f : 0.5f;
        s_wih0[idx] = W_ih0[(gb * H + u) * D_IN + d] * sc;
    }
    for (int idx = tid; idx < H * G; idx += NTHREADS) {
        int k = idx >> 8, r = idx & 255, u = r >> 2, gb = r & 3;
        int row = gb * H + u;
        float sc = (gb == 2) ? 1.0f : 0.5f;
        s_whh0[idx] = W_hh0[row * H + k] * sc;
        s_wih1[idx] = W_ih1[row * H + k] * sc;
        s_whh1[idx] = W_hh1[row * H + k] * sc;
    }
    for (int r = tid; r < G; r += NTHREADS) {
        int u = r >> 2, gb = r & 3, row = gb * H + u;
        float sc = (gb == 2) ? 1.0f : 0.5f;
        s_b0[r] = (b_ih0[row] + b_hh0[row]) * sc;
        s_b1[r] = (b_ih1[row] + b_hh1[row]) * sc;
    }
    for (int i = tid; i < OUT_D * H; i += NTHREADS) s_wfc[i] = W_fc[i];
    if (tid < OUT_D) s_bfc[tid] = b_fc[tid];
    for (int i = tid; i < H * RP; i += NTHREADS) { s_h0[i] = 0.0f; s_h1[i] = 0.0f; }

    // x staging role, PER GROUP: 56 of 64 threads stage this group's 8 rows x 7 dims
    const int  bb      = blockIdx.x * BTILE;
    const bool xactive = ucol < 8 * D_IN;           // 56 stagers per group
    const int  xrl     = ucol / D_IN;               // local row 0..7
    const int  xd      = ucol - xrl * D_IN;         // dim 0..6
    const int  xrow    = r0 + xrl;                  // global row within tile
    const float* xg    = x + ((size_t)(bb + xrow) * T_LEN) * D_IN + xd;

    if (xactive) s_x[xd * XP + xrow] = __ldg(xg);   // prestage x[0]
    __syncthreads();                                 // weights + x[0] visible to all

    // bias packs per gate (duplicated into both FFMA2 lanes), once for all steps
    u64 b0g[4], b1g[4];
    {
        float4 t0 = *(const float4*)&s_b0[ucol * 4];
        b0g[0] = pack2(t0.x); b0g[1] = pack2(t0.y);
        b0g[2] = pack2(t0.z); b0g[3] = pack2(t0.w);
        float4 t1 = *(const float4*)&s_b1[ucol * 4];
        b1g[0] = pack2(t1.x); b1g[1] = pack2(t1.y);
        b1g[2] = pack2(t1.z); b1g[3] = pack2(t1.w);
    }

    float c0[8], c1[8];
    #pragma unroll
    for (int r = 0; r < 8; r++) { c0[r] = 0.f; c1[r] = 0.f; }

    // ============ prologue: t = 0 (h0old = h1old = 0 -> x-only gates) ============
    {
        u64 a0[16];
        #pragma unroll
        for (int g = 0; g < 4; g++)
            #pragma unroll
            for (int p = 0; p < 4; p++) a0[g * 4 + p] = b0g[g];

        #pragma unroll
        for (int d = 0; d < D_IN; d++) {
            float4 wv = *(const float4*)&s_wih0[d * G + ucol * 4];
            ulonglong2 xp = *(const ulonglong2*)&s_x[d * XP + r0];
            ulonglong2 xq = *(const ulonglong2*)&s_x[d * XP + r0 + 4];
            u64 xr[4] = {xp.x, xp.y, xq.x, xq.y};
            float ws[4] = {wv.x, wv.y, wv.z, wv.w};
            #pragma unroll
            for (int g = 0; g < 4; g++) {
                u64 wp = pack2(ws[g]);
                #pragma unroll
                for (int p = 0; p < 4; p++)
                    a0[g * 4 + p] = ffma2(wp, xr[p], a0[g * 4 + p]);
            }
        }

        float h0nv[8];
        #pragma unroll
        for (int p = 0; p < 4; p++) {
            float i0, i1, f0, f1, g0, g1, o0, o1;
            unpack2(a0[0 + p],  i0, i1);
            unpack2(a0[4 + p],  f0, f1);
            unpack2(a0[8 + p],  g0, g1);
            unpack2(a0[12 + p], o0, o1);
            c0[2*p]   = sigp(f0) * c0[2*p]   + sigp(i0) * tanha(g0);
            h0nv[2*p]   = sigp(o0) * tanha(c0[2*p]);
            c0[2*p+1] = sigp(f1) * c0[2*p+1] + sigp(i1) * tanha(g1);
            h0nv[2*p+1] = sigp(o1) * tanha(c0[2*p+1]);
        }

        GBAR(gbar);   // group's reads of s_x[0] done
        *(float4*)&s_h0[ucol * RP + r0]     = make_float4(h0nv[0], h0nv[1], h0nv[2], h0nv[3]);
        *(float4*)&s_h0[ucol * RP + r0 + 4] = make_float4(h0nv[4], h0nv[5], h0nv[6], h0nv[7]);
        if (xactive) s_x[xd * XP + xrow] = __ldg(xg + D_IN);   // stage x[1]
        GBAR(gbar);
    }

    // ============ main loop: iteration t computes h0(t) and h1(t-1) ============
    for (int t = 1; t < T_LEN; t++) {
        // prefetch x(t+1) into register; latency overlaps the whole step
        float xnext = 0.0f;
        if (xactive && t + 1 < T_LEN) xnext = __ldg(xg + (size_t)(t + 1) * D_IN);

        u64 a0[16], a1[16];
        #pragma unroll
        for (int g = 0; g < 4; g++)
            #pragma unroll
            for (int p = 0; p < 4; p++) {
                a0[g * 4 + p] = b0g[g];
                a1[g * 4 + p] = b1g[g];
            }

        // x(t) @ W_ih0^T FIRST: its LDS latency hides under the long k-loop,
        // and it no longer sits on the dependency path right before activations.
        #pragma unroll
        for (int d = 0; d < D_IN; d++) {
            float4 wv = *(const float4*)&s_wih0[d * G + ucol * 4];
            ulonglong2 xp = *(const ulonglong2*)&s_x[d * XP + r0];
            ulonglong2 xq = *(const ulonglong2*)&s_x[d * XP + r0 + 4];
            u64 xr[4] = {xp.x, xp.y, xq.x, xq.y};
            float ws[4] = {wv.x, wv.y, wv.z, wv.w};
            #pragma unroll
            for (int g = 0; g < 4; g++) {
                u64 wp = pack2(ws[g]);
                #pragma unroll
                for (int p = 0; p < 4; p++)
                    a0[g * 4 + p] = ffma2(wp, xr[p], a0[g * 4 + p]);
            }
        }

        // ---- fused GEMMs: Whh0@h0old, Wih1@h0old, Whh1@h1old ----
        // unroll 8: regs at 156 leave ~100 free; deeper unroll doubles the
        // LDS batch ptxas can issue per scoreboard wait (MLP up).
        #pragma unroll 8
        for (int k = 0; k < H; k++) {
            float4 w0v = *(const float4*)&s_whh0[k * G + ucol * 4];
            float4 w1v = *(const float4*)&s_whh1[k * G + ucol * 4];
            float4 w2v = *(const float4*)&s_wih1[k * G + ucol * 4];
            ulonglong2 h0p = *(const ulonglong2*)&s_h0[k * RP + r0];
            ulonglong2 h0q = *(const ulonglong2*)&s_h0[k * RP + r0 + 4];
            ulonglong2 h1p = *(const ulonglong2*)&s_h1[k * RP + r0];
            ulonglong2 h1q = *(const ulonglong2*)&s_h1[k * RP + r0 + 4];
            u64 h0r[4] = {h0p.x, h0p.y, h0q.x, h0q.y};
            u64 h1r[4] = {h1p.x, h1p.y, h1q.x, h1q.y};
            float w0s[4] = {w0v.x, w0v.y, w0v.z, w0v.w};
            float w1s[4] = {w1v.x, w1v.y, w1v.z, w1v.w};
            float w2s[4] = {w2v.x, w2v.y, w2v.z, w2v.w};
            #pragma unroll
            for (int g = 0; g < 4; g++) {
                u64 w0p = pack2(w0s[g]);
                u64 w2p = pack2(w2s[g]);
                u64 w1p = pack2(w1s[g]);
                #pragma unroll
                for (int p = 0; p < 4; p++)
                    a0[g * 4 + p] = ffma2(w0p, h0r[p], a0[g * 4 + p]);
                #pragma unroll
                for (int p = 0; p < 4; p++)
                    a1[g * 4 + p] = ffma2(w2p, h0r[p], a1[g * 4 + p]);
                #pragma unroll
                for (int p = 0; p < 4; p++)
                    a1[g * 4 + p] = ffma2(w1p, h1r[p], a1[g * 4 + p]);
            }
        }

        // ---- both cell updates, interleaved (independent MUFU chains) ----
        float h0nv[8], h1nv[8];
        #pragma unroll
        for (int p = 0; p < 4; p++) {
            float i0, i1, f0, f1, g0, g1, o0, o1;
            unpack2(a0[0 + p],  i0, i1);
            unpack2(a0[4 + p],  f0, f1);
            unpack2(a0[8 + p],  g0, g1);
            unpack2(a0[12 + p], o0, o1);
            c0[2*p]   = sigp(f0) * c0[2*p]   + sigp(i0) * tanha(g0);
            h0nv[2*p]   = sigp(o0) * tanha(c0[2*p]);
            c0[2*p+1] = sigp(f1) * c0[2*p+1] + sigp(i1) * tanha(g1);
            h0nv[2*p+1] = sigp(o1) * tanha(c0[2*p+1]);

            float I0, I1, F0, F1, G0, G1, O0, O1;
            unpack2(a1[0 + p],  I0, I1);
            unpack2(a1[4 + p],  F0, F1);
            unpack2(a1[8 + p],  G0, G1);
            unpack2(a1[12 + p], O0, O1);
            c1[2*p]   = sigp(F0) * c1[2*p]   + sigp(I0) * tanha(G0);
            h1nv[2*p]   = sigp(O0) * tanha(c1[2*p]);
            c1[2*p+1] = sigp(F1) * c1[2*p+1] + sigp(I1) * tanha(G1);
            h1nv[2*p+1] = sigp(O1) * tanha(c1[2*p+1]);
        }

        GBAR(gbar);   // group's reads of s_h0/s_h1/s_x for this step done
        *(float4*)&s_h0[ucol * RP + r0]     = make_float4(h0nv[0], h0nv[1], h0nv[2], h0nv[3]);
        *(float4*)&s_h0[ucol * RP + r0 + 4] = make_float4(h0nv[4], h0nv[5], h0nv[6], h0nv[7]);
        *(float4*)&s_h1[ucol * RP + r0]     = make_float4(h1nv[0], h1nv[1], h1nv[2], h1nv[3]);
        *(float4*)&s_h1[ucol * RP + r0 + 4] = make_float4(h1nv[4], h1nv[5], h1nv[6], h1nv[7]);

        // stage prefetched x(t+1)
        if (xactive && t + 1 < T_LEN)
            s_x[xd * XP + xrow] = xnext;

        GBAR(gbar);   // group's new h0/h1/x visible before next iteration
    }

    // ---- pipeline drain: compute h1(T-1) from h0(T-1), h1(T-2) ----
    {
        u64 a1[16];
        #pragma unroll
        for (int g = 0; g < 4; g++)
            #pragma unroll
            for (int p = 0; p < 4; p++) a1[g * 4 + p] = b1g[g];

        #pragma unroll 8
        for (int k = 0; k < H; k++) {
            float4 w1v = *(const float4*)&s_whh1[k * G + ucol * 4];
            float4 w2v = *(const float4*)&s_wih1[k * G + ucol * 4];
            ulonglong2 h0p = *(const ulonglong2*)&s_h0[k * RP + r0];
            ulonglong2 h0q = *(const ulonglong2*)&s_h0[k * RP + r0 + 4];
            ulonglong2 h1p = *(const ulonglong2*)&s_h1[k * RP + r0];
            ulonglong2 h1q = *(const ulonglong2*)&s_h1[k * RP + r0 + 4];
            u64 h0r[4] = {h0p.x, h0p.y, h0q.x, h0q.y};
            u64 h1r[4] = {h1p.x, h1p.y, h1q.x, h1q.y};
            float w1s[4] = {w1v.x, w1v.y, w1v.z, w1v.w};
            float w2s[4] = {w2v.x, w2v.y, w2v.z, w2v.w};
            #pragma unroll
            for (int g = 0; g < 4; g++) {
                u64 w2p = pack2(w2s[g]);
                u64 w1p = pack2(w1s[g]);
                #pragma unroll
                for (int p = 0; p < 4; p++)
                    a1[g * 4 + p] = ffma2(w2p, h0r[p], a1[g * 4 + p]);
                #pragma unroll
                for (int p = 0; p < 4; p++)
                    a1[g * 4 + p] = ffma2(w1p, h1r[p], a1[g * 4 + p]);
            }
        }

        float h1nv[8];
        #pragma unroll
        for (int p = 0; p < 4; p++) {
            float I0, I1, F0, F1, G0, G1, O0, O1;
            unpack2(a1[0 + p],  I0, I1);
            unpack2(a1[4 + p],  F0, F1);
            unpack2(a1[8 + p],  G0, G1);
            unpack2(a1[12 + p], O0, O1);
            c1[2*p]   = sigp(F0) * c1[2*p]   + sigp(I0) * tanha(G0);
            h1nv[2*p]   = sigp(O0) * tanha(c1[2*p]);
            c1[2*p+1] = sigp(F1) * c1[2*p+1] + sigp(I1) * tanha(G1);
            h1nv[2*p+1] = sigp(O1) * tanha(c1[2*p+1]);
        }
        GBAR(gbar);   // group's reads of s_h1 (h1(T-2)) done
        *(float4*)&s_h1[ucol * RP + r0]     = make_float4(h1nv[0], h1nv[1], h1nv[2], h1nv[3]);
        *(float4*)&s_h1[ucol * RP + r0 + 4] = make_float4(h1nv[4], h1nv[5], h1nv[6], h1nv[7]);
        __syncthreads();   // ALL groups' final h1 visible for the epilogue
    }

    // ---- epilogue: out[b] = h1_last @ W_fc^T + b_fc (warp 0, lane = row) ----
    if (tid < 32) {
        float acc[OUT_D];
        #pragma unroll
        for (int o = 0; o < OUT_D; o++) acc[o] = s_bfc[o];
        #pragma unroll 8
        for (int k = 0; k < H; k++) {
            float hv = s_h1[k * RP + tid];   // h1[row=tid][k]
            #pragma unroll
            for (int o = 0; o < OUT_D; o++) acc[o] += hv * s_wfc[o * H + k];
        }
        int b = bb + tid;
        #pragma unroll
        for (int o = 0; o < OUT_D; o++)
            out[(size_t)b * OUT_D + o] = acc[o];
    }
}

extern "C" void kernel_launch(void* const* d_in, const int* in_sizes, int n_in,
                              void* d_out, int out_size)
{
    const float* x     = (const float*)d_in[0];
    const float* W_ih0 = (const float*)d_in[1];
    const float* W_hh0 = (const float*)d_in[2];
    const float* b_ih0 = (const float*)d_in[3];
    const float* b_hh0 = (const float*)d_in[4];
    const float* W_ih1 = (const float*)d_in[5];
    const float* W_hh1 = (const float*)d_in[6];
    const float* b_ih1 = (const float*)d_in[7];
    const float* b_hh1 = (const float*)d_in[8];
    const float* W_fc  = (const float*)d_in[9];
    const float* b_fc  = (const float*)d_in[10];
    float* out = (float*)d_out;

    const size_t smem_floats = (size_t)D_IN * G + 3 * (size_t)H * G + 2 * G
                             + OUT_D * H + 8 + 2 * (size_t)H * RP + D_IN * XP;
    const size_t smem_bytes = smem_floats * sizeof(float);   // 226,208 B

    cudaFuncSetAttribute(lstm_fused_kernel,
                         cudaFuncAttributeMaxDynamicSharedMemorySize,
                         (int)smem_bytes);

    lstm_fused_kernel<<<B_TOT / BTILE, NTHREADS, smem_bytes>>>(
        x, W_ih0, W_hh0, b_ih0, b_hh0,
        W_ih1, W_hh1, b_ih1, b_hh1, W_fc, b_fc, out);
}

// round 16
// speedup vs baseline: 1.0505x; 1.0004x over previous
#include <cuda_runtime.h>

// Problem constants
#define B_TOT    4096
#define T_LEN    512
#define D_IN     7
#define H        64
#define G        256      // 4*H gates per layer
#define OUT_D    4
#define BTILE    32       // batch rows per CTA
#define NTHREADS 256      // thread = (8 batch rows) x (1 unit = 4 gates)
#define RP       36       // h smem pitch in floats
#define XP       32       // x smem pitch: s_x[d*XP + row]

typedef unsigned long long u64;

// group barrier: 64 threads (2 warps) of one batch-row group
#define GBAR(id) asm volatile("bar.sync %0, 64;" :: "r"(id) : "memory")

__device__ __forceinline__ u64 pack2(float v) {
    u64 r; asm("mov.b64 %0, {%1, %1};" : "=l"(r) : "f"(v)); return r;
}
__device__ __forceinline__ void unpack2(u64 v, float& a, float& b) {
    asm("mov.b64 {%0, %1}, %2;" : "=f"(a), "=f"(b) : "l"(v));
}
__device__ __forceinline__ u64 ffma2(u64 a, u64 b, u64 c) {
    u64 d; asm("fma.rn.f32x2 %0, %1, %2, %3;" : "=l"(d) : "l"(a), "l"(b), "l"(c)); return d;
}

// single-MUFU activations; sigmoid inputs arrive PRE-SCALED by 0.5
// (i/f/o weight rows and biases are multiplied by 0.5 at staging time):
//   sigma(z) = 0.5*tanh(z/2) + 0.5,  accumulator already holds z/2.
__device__ __forceinline__ float tanha(float x) {
    float y; asm("tanh.approx.f32 %0, %1;" : "=f"(y) : "f"(x)); return y;
}
__device__ __forceinline__ float sigp(float half_z) {
    return fmaf(tanha(half_z), 0.5f, 0.5f);
}

__global__ __launch_bounds__(NTHREADS, 1)
void lstm_fused_kernel(const float* __restrict__ x,
                       const float* __restrict__ W_ih0, const float* __restrict__ W_hh0,
                       const float* __restrict__ b_ih0, const float* __restrict__ b_hh0,
                       const float* __restrict__ W_ih1, const float* __restrict__ W_hh1,
                       const float* __restrict__ b_ih1, const float* __restrict__ b_hh1,
                       const float* __restrict__ W_fc,  const float* __restrict__ b_fc,
                       float* __restrict__ out)
{
    extern __shared__ float smem[];
    // weight layout: [k][unit][gate i,f,g,o] -> idx = k*256 + u*4 + g
    float* s_wih0 = smem;                    // [7][256]
    float* s_whh0 = s_wih0 + D_IN * G;       // [64][256]
    float* s_wih1 = s_whh0 + H * G;          // [64][256]
    float* s_whh1 = s_wih1 + H * G;          // [64][256]
    float* s_b0   = s_whh1 + H * G;          // [256]
    float* s_b1   = s_b0 + G;                // [256]
    float* s_wfc  = s_b1 + G;                // [4][64]
    float* s_bfc  = s_wfc + OUT_D * H;       // [8]
    float* s_h0   = s_bfc + 8;               // [64][RP]  [unit][row]
    float* s_h1   = s_h0 + H * RP;           // [64][RP]
    float* s_x    = s_h1 + H * RP;           // [7][XP]   [d][row]

    const int tid  = threadIdx.x;
    const int urow = tid >> 6;               // 0..3 : batch-row group (64 thr = 2 warps)
    const int ucol = tid & 63;               // 0..63: hidden unit
    const int r0   = urow * 8;               // first of this thread's 8 rows
    const int gbar = urow + 1;               // named barrier id for this group

    // ---- stage weights into smem, transposed + gate-interleaved ----
    // i/f/o rows (gb != 2) are pre-scaled by 0.5 for the sigmoid identity.
    for (int idx = tid; idx < D_IN * G; idx += NTHREADS) {
        int d = idx >> 8, r = idx & 255, u = r >> 2, gb = r & 3;
        float sc = (gb == 2) ? 1.0f : 0.5f;
        s_wih0[idx] = W_ih0[(gb * H + u) * D_IN + d] * sc;
    }
    for (int idx = tid; idx < H * G; idx += NTHREADS) {
        int k = idx >> 8, r = idx & 255, u = r >> 2, gb = r & 3;
        int row = gb * H + u;
        float sc = (gb == 2) ? 1.0f : 0.5f;
        s_whh0[idx] = W_hh0[row * H + k] * sc;
        s_wih1[idx] = W_ih1[row * H + k] * sc;
        s_whh1[idx] = W_hh1[row * H + k] * sc;
    }
    for (int r = tid; r < G; r += NTHREADS) {
        int u = r >> 2, gb = r & 3, row = gb * H + u;
        float sc = (gb == 2) ? 1.0f : 0.5f;
        s_b0[r] = (b_ih0[row] + b_hh0[row]) * sc;
        s_b1[r] = (b_ih1[row] + b_hh1[row]) * sc;
    }
    for (int i = tid; i < OUT_D * H; i += NTHREADS) s_wfc[i] = W_fc[i];
    if (tid < OUT_D) s_bfc[tid] = b_fc[tid];
    for (int i = tid; i < H * RP; i += NTHREADS) { s_h0[i] = 0.0f; s_h1[i] = 0.0f; }

    // x staging role, PER GROUP: 56 of 64 threads stage this group's 8 rows x 7 dims
    const int  bb      = blockIdx.x * BTILE;
    const bool xactive = ucol < 8 * D_IN;           // 56 stagers per group
    const int  xrl     = ucol / D_IN;               // local row 0..7
    const int  xd      = ucol - xrl * D_IN;         // dim 0..6
    const int  xrow    = r0 + xrl;                  // global row within tile
    const float* xg    = x + ((size_t)(bb + xrow) * T_LEN) * D_IN + xd;

    if (xactive) s_x[xd * XP + xrow] = __ldg(xg);   // prestage x[0]
    __syncthreads();                                 // weights + x[0] visible to all

    // bias packs per gate (duplicated into both FFMA2 lanes), once for all steps
    u64 b0g[4], b1g[4];
    {
        float4 t0 = *(const float4*)&s_b0[ucol * 4];
        b0g[0] = pack2(t0.x); b0g[1] = pack2(t0.y);
        b0g[2] = pack2(t0.z); b0g[3] = pack2(t0.w);
        float4 t1 = *(const float4*)&s_b1[ucol * 4];
        b1g[0] = pack2(t1.x); b1g[1] = pack2(t1.y);
        b1g[2] = pack2(t1.z); b1g[3] = pack2(t1.w);
    }

    float c0[8], c1[8];
    #pragma unroll
    for (int r = 0; r < 8; r++) { c0[r] = 0.f; c1[r] = 0.f; }

    // ============ prologue: t = 0 (h0old = h1old = 0 -> x-only gates) ============
    {
        u64 a0[16];
        #pragma unroll
        for (int g = 0; g < 4; g++)
            #pragma unroll
            for (int p = 0; p < 4; p++) a0[g * 4 + p] = b0g[g];

        #pragma unroll
        for (int d = 0; d < D_IN; d++) {
            float4 wv = *(const float4*)&s_wih0[d * G + ucol * 4];
            ulonglong2 xp = *(const ulonglong2*)&s_x[d * XP + r0];
            ulonglong2 xq = *(const ulonglong2*)&s_x[d * XP + r0 + 4];
            u64 xr[4] = {xp.x, xp.y, xq.x, xq.y};
            float ws[4] = {wv.x, wv.y, wv.z, wv.w};
            #pragma unroll
            for (int g = 0; g < 4; g++) {
                u64 wp = pack2(ws[g]);
                #pragma unroll
                for (int p = 0; p < 4; p++)
                    a0[g * 4 + p] = ffma2(wp, xr[p], a0[g * 4 + p]);
            }
        }

        GBAR(gbar);   // all group reads of s_x[0] complete (accumulators hold them)

        #pragma unroll
        for (int h4 = 0; h4 < 2; h4++) {      // compute+store one float4 at a time
            float hn[4];
            #pragma unroll
            for (int j = 0; j < 2; j++) {
                int p = h4 * 2 + j;
                float i0, i1, f0, f1, g0, g1, o0, o1;
                unpack2(a0[0 + p],  i0, i1);
                unpack2(a0[4 + p],  f0, f1);
                unpack2(a0[8 + p],  g0, g1);
                unpack2(a0[12 + p], o0, o1);
                c0[2*p]   = sigp(f0) * c0[2*p]   + sigp(i0) * tanha(g0);
                hn[2*j]   = sigp(o0) * tanha(c0[2*p]);
                c0[2*p+1] = sigp(f1) * c0[2*p+1] + sigp(i1) * tanha(g1);
                hn[2*j+1] = sigp(o1) * tanha(c0[2*p+1]);
            }
            *(float4*)&s_h0[ucol * RP + r0 + h4 * 4] = make_float4(hn[0], hn[1], hn[2], hn[3]);
        }
        if (xactive) s_x[xd * XP + xrow] = __ldg(xg + D_IN);   // stage x[1]
        GBAR(gbar);
    }

    // ============ main loop: iteration t computes h0(t) and h1(t-1) ============
    for (int t = 1; t < T_LEN; t++) {
        // prefetch x(t+1) into register; latency overlaps the whole step
        float xnext = 0.0f;
        if (xactive && t + 1 < T_LEN) xnext = __ldg(xg + (size_t)(t + 1) * D_IN);

        u64 a0[16], a1[16];
        #pragma unroll
        for (int g = 0; g < 4; g++)
            #pragma unroll
            for (int p = 0; p < 4; p++) {
                a0[g * 4 + p] = b0g[g];
                a1[g * 4 + p] = b1g[g];
            }

        // x(t) @ W_ih0^T FIRST: its LDS latency hides under the long k-loop.
        #pragma unroll
        for (int d = 0; d < D_IN; d++) {
            float4 wv = *(const float4*)&s_wih0[d * G + ucol * 4];
            ulonglong2 xp = *(const ulonglong2*)&s_x[d * XP + r0];
            ulonglong2 xq = *(const ulonglong2*)&s_x[d * XP + r0 + 4];
            u64 xr[4] = {xp.x, xp.y, xq.x, xq.y};
            float ws[4] = {wv.x, wv.y, wv.z, wv.w};
            #pragma unroll
            for (int g = 0; g < 4; g++) {
                u64 wp = pack2(ws[g]);
                #pragma unroll
                for (int p = 0; p < 4; p++)
                    a0[g * 4 + p] = ffma2(wp, xr[p], a0[g * 4 + p]);
            }
        }

        // ---- fused GEMMs: Whh0@h0old, Wih1@h0old, Whh1@h1old ----
        #pragma unroll 8
        for (int k = 0; k < H; k++) {
            float4 w0v = *(const float4*)&s_whh0[k * G + ucol * 4];
            float4 w1v = *(const float4*)&s_whh1[k * G + ucol * 4];
            float4 w2v = *(const float4*)&s_wih1[k * G + ucol * 4];
            ulonglong2 h0p = *(const ulonglong2*)&s_h0[k * RP + r0];
            ulonglong2 h0q = *(const ulonglong2*)&s_h0[k * RP + r0 + 4];
            ulonglong2 h1p = *(const ulonglong2*)&s_h1[k * RP + r0];
            ulonglong2 h1q = *(const ulonglong2*)&s_h1[k * RP + r0 + 4];
            u64 h0r[4] = {h0p.x, h0p.y, h0q.x, h0q.y};
            u64 h1r[4] = {h1p.x, h1p.y, h1q.x, h1q.y};
            float w0s[4] = {w0v.x, w0v.y, w0v.z, w0v.w};
            float w1s[4] = {w1v.x, w1v.y, w1v.z, w1v.w};
            float w2s[4] = {w2v.x, w2v.y, w2v.z, w2v.w};
            #pragma unroll
            for (int g = 0; g < 4; g++) {
                u64 w0p = pack2(w0s[g]);
                u64 w2p = pack2(w2s[g]);
                u64 w1p = pack2(w1s[g]);
                #pragma unroll
                for (int p = 0; p < 4; p++)
                    a0[g * 4 + p] = ffma2(w0p, h0r[p], a0[g * 4 + p]);
                #pragma unroll
                for (int p = 0; p < 4; p++)
                    a1[g * 4 + p] = ffma2(w2p, h0r[p], a1[g * 4 + p]);
                #pragma unroll
                for (int p = 0; p < 4; p++)
                    a1[g * 4 + p] = ffma2(w1p, h1r[p], a1[g * 4 + p]);
            }
        }

        // ---- EARLY barrier: all group reads of s_h0/s_h1/s_x are complete here
        // (accumulators hold everything). Both warps arrive before their MUFU
        // tails, so the tails overlap in the post-barrier region and each
        // float4 store issues as soon as it's computed.
        GBAR(gbar);

        // ---- activations + stores, interleaved per float4 ----
        #pragma unroll
        for (int h4 = 0; h4 < 2; h4++) {
            float hn0[4], hn1[4];
            #pragma unroll
            for (int j = 0; j < 2; j++) {
                int p = h4 * 2 + j;
                float i0, i1, f0, f1, g0, g1, o0, o1;
                unpack2(a0[0 + p],  i0, i1);
                unpack2(a0[4 + p],  f0, f1);
                unpack2(a0[8 + p],  g0, g1);
                unpack2(a0[12 + p], o0, o1);
                c0[2*p]   = sigp(f0) * c0[2*p]   + sigp(i0) * tanha(g0);
                hn0[2*j]   = sigp(o0) * tanha(c0[2*p]);
                c0[2*p+1] = sigp(f1) * c0[2*p+1] + sigp(i1) * tanha(g1);
                hn0[2*j+1] = sigp(o1) * tanha(c0[2*p+1]);

                float I0, I1, F0, F1, G0, G1, O0, O1;
                unpack2(a1[0 + p],  I0, I1);
                unpack2(a1[4 + p],  F0, F1);
                unpack2(a1[8 + p],  G0, G1);
                unpack2(a1[12 + p], O0, O1);
                c1[2*p]   = sigp(F0) * c1[2*p]   + sigp(I0) * tanha(G0);
                hn1[2*j]   = sigp(O0) * tanha(c1[2*p]);
                c1[2*p+1] = sigp(F1) * c1[2*p+1] + sigp(I1) * tanha(G1);
                hn1[2*j+1] = sigp(O1) * tanha(c1[2*p+1]);
            }
            *(float4*)&s_h0[ucol * RP + r0 + h4 * 4] = make_float4(hn0[0], hn0[1], hn0[2], hn0[3]);
            *(float4*)&s_h1[ucol * RP + r0 + h4 * 4] = make_float4(hn1[0], hn1[1], hn1[2], hn1[3]);
        }

        // stage prefetched x(t+1) (s_x readers finished before GBAR#1)
        if (xactive && t + 1 < T_LEN)
            s_x[xd * XP + xrow] = xnext;

        GBAR(gbar);   // group's new h0/h1/x visible before next iteration
    }

    // ---- pipeline drain: compute h1(T-1) from h0(T-1), h1(T-2) ----
    {
        u64 a1[16];
        #pragma unroll
        for (int g = 0; g < 4; g++)
            #pragma unroll
            for (int p = 0; p < 4; p++) a1[g * 4 + p] = b1g[g];

        #pragma unroll 8
        for (int k = 0; k < H; k++) {
            float4 w1v = *(const float4*)&s_whh1[k * G + ucol * 4];
            float4 w2v = *(const float4*)&s_wih1[k * G + ucol * 4];
            ulonglong2 h0p = *(const ulonglong2*)&s_h0[k * RP + r0];
            ulonglong2 h0q = *(const ulonglong2*)&s_h0[k * RP + r0 + 4];
            ulonglong2 h1p = *(const ulonglong2*)&s_h1[k * RP + r0];
            ulonglong2 h1q = *(const ulonglong2*)&s_h1[k * RP + r0 + 4];
            u64 h0r[4] = {h0p.x, h0p.y, h0q.x, h0q.y};
            u64 h1r[4] = {h1p.x, h1p.y, h1q.x, h1q.y};
            float w1s[4] = {w1v.x, w1v.y, w1v.z, w1v.w};
            float w2s[4] = {w2v.x, w2v.y, w2v.z, w2v.w};
            #pragma unroll
            for (int g = 0; g < 4; g++) {
                u64 w2p = pack2(w2s[g]);
                u64 w1p = pack2(w1s[g]);
                #pragma unroll
                for (int p = 0; p < 4; p++)
                    a1[g * 4 + p] = ffma2(w2p, h0r[p], a1[g * 4 + p]);
                #pragma unroll
                for (int p = 0; p < 4; p++)
                    a1[g * 4 + p] = ffma2(w1p, h1r[p], a1[g * 4 + p]);
            }
        }

        GBAR(gbar);   // group's reads of s_h1 (h1(T-2)) done

        #pragma unroll
        for (int h4 = 0; h4 < 2; h4++) {
            float hn[4];
            #pragma unroll
            for (int j = 0; j < 2; j++) {
                int p = h4 * 2 + j;
                float I0, I1, F0, F1, G0, G1, O0, O1;
                unpack2(a1[0 + p],  I0, I1);
                unpack2(a1[4 + p],  F0, F1);
                unpack2(a1[8 + p],  G0, G1);
                unpack2(a1[12 + p], O0, O1);
                c1[2*p]   = sigp(F0) * c1[2*p]   + sigp(I0) * tanha(G0);
                hn[2*j]   = sigp(O0) * tanha(c1[2*p]);
                c1[2*p+1] = sigp(F1) * c1[2*p+1] + sigp(I1) * tanha(G1);
                hn[2*j+1] = sigp(O1) * tanha(c1[2*p+1]);
            }
            *(float4*)&s_h1[ucol * RP + r0 + h4 * 4] = make_float4(hn[0], hn[1], hn[2], hn[3]);
        }
        __syncthreads();   // ALL groups' final h1 visible for the epilogue
    }

    // ---- epilogue: out[b] = h1_last @ W_fc^T + b_fc (warp 0, lane = row) ----
    if (tid < 32) {
        float acc[OUT_D];
        #pragma unroll
        for (int o = 0; o < OUT_D; o++) acc[o] = s_bfc[o];
        #pragma unroll 8
        for (int k = 0; k < H; k++) {
            float hv = s_h1[k * RP + tid];   // h1[row=tid][k]
            #pragma unroll
            for (int o = 0; o < OUT_D; o++) acc[o] += hv * s_wfc[o * H + k];
        }
        int b = bb + tid;
        #pragma unroll
        for (int o = 0; o < OUT_D; o++)
            out[(size_t)b * OUT_D + o] = acc[o];
    }
}

extern "C" void kernel_launch(void* const* d_in, const int* in_sizes, int n_in,
                              void* d_out, int out_size)
{
    const float* x     = (const float*)d_in[0];
    const float* W_ih0 = (const float*)d_in[1];
    const float* W_hh0 = (const float*)d_in[2];
    const float* b_ih0 = (const float*)d_in[3];
    const float* b_hh0 = (const float*)d_in[4];
    const float* W_ih1 = (const float*)d_in[5];
    const float* W_hh1 = (const float*)d_in[6];
    const float* b_ih1 = (const float*)d_in[7];
    const float* b_hh1 = (const float*)d_in[8];
    const float* W_fc  = (const float*)d_in[9];
    const float* b_fc  = (const float*)d_in[10];
    float* out = (float*)d_out;

    const size_t smem_floats = (size_t)D_IN * G + 3 * (size_t)H * G + 2 * G
                             + OUT_D * H + 8 + 2 * (size_t)H * RP + D_IN * XP;
    const size_t smem_bytes = smem_floats * sizeof(float);   // 226,208 B

    cudaFuncSetAttribute(lstm_fused_kernel,
                         cudaFuncAttributeMaxDynamicSharedMemorySize,
                         (int)smem_bytes);

    lstm_fused_kernel<<<B_TOT / BTILE, NTHREADS, smem_bytes>>>(
        x, W_ih0, W_hh0, b_ih0, b_hh0,
        W_ih1, W_hh1, b_ih1, b_hh1, W_fc, b_fc, out);
}